// round 14
// baseline (speedup 1.0000x reference)
#include <cuda_runtime.h>
#include <cuda_bf16.h>
#include <cstdint>

#define BB 128
#define TT 2048
#define HH 512
#define MM (BB*TT)

// ---------------- device scratch (no allocations allowed) ----------------
__device__ __align__(16) __nv_bfloat16 g_Xh[(size_t)MM*HH];  // bf16(X)
__device__ __align__(16) __nv_bfloat16 g_Xl[(size_t)MM*HH];  // bf16(X - Xh)
__device__ __align__(16) __nv_bfloat16 g_Wh[HH*HH];
__device__ __align__(16) __nv_bfloat16 g_Wl[HH*HH];
__device__ __align__(16) float2 g_vb[HH];          // {v[o], bsum[o]*2*log2(e)}
__device__ float g_score[MM];
__device__ __align__(16) float g_cpart[16*BB*HH];

#define SW128(o) ((o) ^ (((o) >> 3) & 0x70))
#define TWO_LOG2E 2.885390081777927f

__device__ __forceinline__ uint32_t smem_u32(const void* p) {
    uint32_t a;
    asm("{ .reg .u64 t; cvta.to.shared.u64 t, %1; cvt.u32.u64 %0, t; }" : "=r"(a) : "l"(p));
    return a;
}
__device__ __forceinline__ uint32_t pack2bf(float lo, float hi) {
    uint32_t r;   // low-address element in low 16 bits
    asm("cvt.rn.bf16x2.f32 %0, %1, %2;" : "=r"(r) : "f"(hi), "f"(lo));
    return r;
}
__device__ __forceinline__ void ldsm4(uint32_t* r, uint32_t addr) {
    asm volatile("ldmatrix.sync.aligned.m8n8.x4.shared.b16 {%0,%1,%2,%3}, [%4];"
                 : "=r"(r[0]), "=r"(r[1]), "=r"(r[2]), "=r"(r[3]) : "r"(addr));
}
__device__ __forceinline__ void mma16816(float* c, const uint32_t* a, const uint32_t* b) {
    asm volatile("mma.sync.aligned.m16n8k16.row.col.f32.bf16.bf16.f32 "
                 "{%0,%1,%2,%3}, {%4,%5,%6,%7}, {%8,%9}, {%0,%1,%2,%3};"
                 : "+f"(c[0]), "+f"(c[1]), "+f"(c[2]), "+f"(c[3])
                 : "r"(a[0]), "r"(a[1]), "r"(a[2]), "r"(a[3]), "r"(b[0]), "r"(b[1]));
}
__device__ __forceinline__ void cpasync16(uint32_t saddr, const void* gptr) {
    asm volatile("cp.async.cg.shared.global [%0], [%1], 16;" :: "r"(saddr), "l"(gptr) : "memory");
}

// ---------------- K0: prep X — split into bf16 hi/lo planes ----------------
__global__ void prepX_kernel(const float* __restrict__ X) {
    size_t i0 = (size_t)blockIdx.x * 2048 + threadIdx.x;
    const float4* X4 = (const float4*)X;
    uint2* H2 = (uint2*)g_Xh;
    uint2* L2 = (uint2*)g_Xl;
#pragma unroll
    for (int j = 0; j < 8; j++) {
        size_t i = i0 + (size_t)j * 256;
        float4 x = X4[i];
        uint32_t h0 = pack2bf(x.x, x.y);
        uint32_t h1 = pack2bf(x.z, x.w);
        float rx = x.x - __uint_as_float(h0 << 16);
        float ry = x.y - __uint_as_float(h0 & 0xffff0000u);
        float rz = x.z - __uint_as_float(h1 << 16);
        float rw = x.w - __uint_as_float(h1 & 0xffff0000u);
        H2[i] = make_uint2(h0, h1);
        L2[i] = make_uint2(pack2bf(rx, ry), pack2bf(rz, rw));
    }
}

// ---------------- K1: prep — Wsum split into bf16 hi/lo; vb table ----------------
__global__ void prep_kernel(const float* __restrict__ Wa_w, const float* __restrict__ Wa_b,
                            const float* __restrict__ Ua_w, const float* __restrict__ Ua_b,
                            const float* __restrict__ Va_w) {
    int i = blockIdx.x * blockDim.x + threadIdx.x;
    if (i < HH * HH) {
        float w = Wa_w[i] + Ua_w[i];
        __nv_bfloat16 h = __float2bfloat16_rn(w);
        g_Wh[i] = h;
        g_Wl[i] = __float2bfloat16_rn(w - __bfloat162float(h));
    }
    if (i < HH) {
        float b = Wa_b[i] + Ua_b[i];
        g_vb[i] = make_float2(Va_w[i], b * TWO_LOG2E);
    }
}

// ---------------- K2: fused score GEMM, pure cp.async 3-stage pipeline ----------------
// score[m] = sum_o v[o] * tanh(bsum[o] + sum_k X[m,k]*Wsum[o,k])
// CTA: M=128, flat loop over 64 chunks: g = nb*16 + kc (4 N-passes x 16 K-chunks of 32).
// Tile rows interleave hi|lo: [32k hi (64B) | 32k lo (64B)] = 128B -> SW128 (R12-proven).
// SMEM: 3 stages x (A 16K + B 16K) = 96KB. 2 CTAs/SM (128-reg cap).
// No in-kernel conversion: A planes pre-split by prepX_kernel; both A and B cp.async.

#define SM_DYN (3*32768 + 1024)

__device__ __forceinline__ void cpA(uint32_t stage, size_t m_base, int kc, int tid) {
    const char* gh = (const char*)g_Xh;
    const char* gl = (const char*)g_Xl;
#pragma unroll
    for (int i = 0; i < 4; i++) {
        int u    = tid + i * 256;        // 0..1023 = m*8 + part*4 + uu
        int m    = u >> 3;
        int part = (u >> 2) & 1;
        int uu   = u & 3;
        size_t gbyte = (m_base + m) * 1024 + (size_t)kc * 64 + uu * 16;
        const char* src = part ? (gl + gbyte) : (gh + gbyte);
        cpasync16(stage + SW128(m * 128 + part * 64 + uu * 16), src);
    }
}

__device__ __forceinline__ void cpB(uint32_t stage, int nb, int kc, int tid) {
    const uint32_t B = stage + 16384;
    const char* gh = (const char*)g_Wh;
    const char* gl = (const char*)g_Wl;
#pragma unroll
    for (int i = 0; i < 4; i++) {
        int u    = tid + i * 256;        // 0..1023 = o*8 + part*4 + uu
        int o    = u >> 3;
        int part = (u >> 2) & 1;
        int uu   = u & 3;
        size_t gbyte = (size_t)((nb * 128 + o) * 512 + kc * 32) * 2 + uu * 16;
        const char* src = part ? (gl + gbyte) : (gh + gbyte);
        cpasync16(B + SW128(o * 128 + part * 64 + uu * 16), src);
    }
}

__global__ __launch_bounds__(256, 2)
void score_kernel() {
    extern __shared__ __align__(1024) char smem[];
    __shared__ float score_sm[128];
    const uint32_t sb = smem_u32(smem);
    const uint32_t abase = (sb + 1023u) & ~1023u;   // 1024-aligned stage base
    const int tid  = threadIdx.x;
    const int lane = tid & 31;
    const int wid  = tid >> 5;
    const int wm   = wid & 3;                        // m-warp 0..3 (32 rows each)
    const int wn   = wid >> 2;                       // n-warp 0..1 (64 cols each)
    const size_t m_base = (size_t)blockIdx.x * 128;

    if (tid < 128) score_sm[tid] = 0.0f;

    // ldmatrix per-lane offsets within swizzled 128B-row tiles
    const uint32_t xw = (uint32_t)((lane & 7) << 4);
    uint32_t aoff[2];
#pragma unroll
    for (int mf = 0; mf < 2; mf++) {
        int mrow = wm * 32 + mf * 16 + (lane & 15);
        aoff[mf] = mrow * 128 + ((lane >> 4) << 4);
    }
    uint32_t boff[4];
#pragma unroll
    for (int nf = 0; nf < 4; nf++) {
        int nrow = wn * 64 + nf * 16 + (lane & 7) + ((lane >> 4) << 3);
        boff[nf] = nrow * 128 + (((lane >> 3) & 1) << 4);
    }

    float c[2][8][4];

    // prologue: prefetch chunks 0 and 1
    cpA(abase, m_base, 0, tid);            cpB(abase, 0, 0, tid);
    asm volatile("cp.async.commit_group;");
    cpA(abase + 32768, m_base, 1, tid);    cpB(abase + 32768, 0, 1, tid);
    asm volatile("cp.async.commit_group;");

    for (int g = 0; g < 64; g++) {
        const int kc = g & 15;
        const int nb = g >> 4;
        const uint32_t stage = abase + (uint32_t)(g % 3) * 32768;

        asm volatile("cp.async.wait_group 1;" ::: "memory");
        __syncthreads();   // stage data visible; all warps done with chunk g-1

        if (g + 2 < 64) {
            const int g2 = g + 2;
            const uint32_t st2 = abase + (uint32_t)(g2 % 3) * 32768;
            cpA(st2, m_base, g2 & 15, tid);
            cpB(st2, g2 >> 4, g2 & 15, tid);
            asm volatile("cp.async.commit_group;");
        }

        if (kc == 0) {
#pragma unroll
            for (int mf = 0; mf < 2; mf++)
#pragma unroll
                for (int j = 0; j < 8; j++)
#pragma unroll
                    for (int q = 0; q < 4; q++) c[mf][j][q] = 0.0f;
        }

        const uint32_t A = stage;
        const uint32_t B = stage + 16384;
#pragma unroll
        for (int k16 = 0; k16 < 2; k16++) {
            uint32_t ah[2][4], al[2][4], bb[4][4];
#pragma unroll
            for (int mf = 0; mf < 2; mf++) {
                ldsm4(ah[mf], A + ((aoff[mf] + k16 * 32) ^ xw));          // Xh
                ldsm4(al[mf], A + ((aoff[mf] + 64 + k16 * 32) ^ xw));     // Xl
            }
#pragma unroll
            for (int nf = 0; nf < 4; nf++)
                ldsm4(bb[nf], B + ((boff[nf] + k16 * 32) ^ xw));          // Wh
#pragma unroll
            for (int mf = 0; mf < 2; mf++)
#pragma unroll
                for (int nf = 0; nf < 4; nf++) {
                    mma16816(c[mf][2 * nf],     ah[mf], &bb[nf][0]);
                    mma16816(c[mf][2 * nf + 1], ah[mf], &bb[nf][2]);
                }
#pragma unroll
            for (int mf = 0; mf < 2; mf++)
#pragma unroll
                for (int nf = 0; nf < 4; nf++) {
                    mma16816(c[mf][2 * nf],     al[mf], &bb[nf][0]);      // Xl*Wh
                    mma16816(c[mf][2 * nf + 1], al[mf], &bb[nf][2]);
                }
#pragma unroll
            for (int nf = 0; nf < 4; nf++)
                ldsm4(bb[nf], B + ((boff[nf] + 64 + k16 * 32) ^ xw));     // Wl
#pragma unroll
            for (int mf = 0; mf < 2; mf++)
#pragma unroll
                for (int nf = 0; nf < 4; nf++) {
                    mma16816(c[mf][2 * nf],     ah[mf], &bb[nf][0]);      // Xh*Wl
                    mma16816(c[mf][2 * nf + 1], ah[mf], &bb[nf][2]);
                }
        }

        if (kc == 15) {
            // fused epilogue for pass nb: score += v[o]*tanh(acc + b[o])
            const int quad = lane & 3;
#pragma unroll
            for (int mf = 0; mf < 2; mf++) {
                float s0 = 0.0f, s1 = 0.0f;
#pragma unroll
                for (int j = 0; j < 8; j++) {
#pragma unroll
                    for (int col = 0; col < 2; col++) {
                        int o = nb * 128 + wn * 64 + j * 8 + quad * 2 + col;
                        float2 vbv = __ldg(&g_vb[o]);
                        float x0 = fmaf(c[mf][j][col],     TWO_LOG2E, vbv.y);
                        float x1 = fmaf(c[mf][j][col + 2], TWO_LOG2E, vbv.y);
                        float e0, e1, r0, r1;
                        asm("ex2.approx.f32 %0, %1;" : "=f"(e0) : "f"(x0));
                        asm("ex2.approx.f32 %0, %1;" : "=f"(e1) : "f"(x1));
                        asm("rcp.approx.f32 %0, %1;" : "=f"(r0) : "f"(e0 + 1.0f));
                        asm("rcp.approx.f32 %0, %1;" : "=f"(r1) : "f"(e1 + 1.0f));
                        s0 += vbv.x - 2.0f * vbv.x * r0;   // v*tanh
                        s1 += vbv.x - 2.0f * vbv.x * r1;
                    }
                }
                s0 += __shfl_xor_sync(0xffffffffu, s0, 1);
                s0 += __shfl_xor_sync(0xffffffffu, s0, 2);
                s1 += __shfl_xor_sync(0xffffffffu, s1, 1);
                s1 += __shfl_xor_sync(0xffffffffu, s1, 2);
                if (quad == 0) {
                    int r = wm * 32 + mf * 16 + (lane >> 2);
                    atomicAdd(&score_sm[r], s0);
                    atomicAdd(&score_sm[r + 8], s1);
                }
            }
        }
    }

    __syncthreads();
    if (tid < 128) g_score[m_base + tid] = score_sm[tid];
}

// ---------------- K3: per-batch softmax over T ----------------
__global__ void softmax_kernel(float* __restrict__ aw_out) {
    __shared__ float sh[TT];
    __shared__ float red[256];
    const int b = blockIdx.x;
    const int tid = threadIdx.x;
    const float* s = g_score + (size_t)b * TT;

    float mx = -1e30f;
    for (int t = tid; t < TT; t += 256) {
        float v = s[t];
        sh[t] = v;
        mx = fmaxf(mx, v);
    }
    red[tid] = mx;
    __syncthreads();
    for (int o = 128; o > 0; o >>= 1) {
        if (tid < o) red[tid] = fmaxf(red[tid], red[tid + o]);
        __syncthreads();
    }
    mx = red[0];
    __syncthreads();

    float sum = 0.0f;
    for (int t = tid; t < TT; t += 256) {
        float e = __expf(sh[t] - mx);
        sh[t] = e;
        sum += e;
    }
    red[tid] = sum;
    __syncthreads();
    for (int o = 128; o > 0; o >>= 1) {
        if (tid < o) red[tid] += red[tid + o];
        __syncthreads();
    }
    float inv = 1.0f / red[0];
    for (int t = tid; t < TT; t += 256)
        aw_out[(size_t)b * TT + t] = sh[t] * inv;
}

// ---------------- K4: context partials (float4/thread), 16 T-chunks ----------------
__global__ void context_part_kernel(const float* __restrict__ X,
                                    const float* __restrict__ aw) {
    const int blk = blockIdx.x;           // b*16 + tb
    const int b  = blk >> 4;
    const int tb = blk & 15;
    const float4* xp = (const float4*)(X + (size_t)b * TT * HH + (size_t)tb * 128 * HH)
                       + threadIdx.x;     // thread covers h = tid*4..tid*4+3
    const float* a = aw + (size_t)b * TT + tb * 128;

    float4 acc = make_float4(0.f, 0.f, 0.f, 0.f);
#pragma unroll 8
    for (int t = 0; t < 128; t++) {
        float av = a[t];
        float4 x = xp[(size_t)t * 128];
        acc.x = fmaf(av, x.x, acc.x);
        acc.y = fmaf(av, x.y, acc.y);
        acc.z = fmaf(av, x.z, acc.z);
        acc.w = fmaf(av, x.w, acc.w);
    }
    ((float4*)g_cpart)[((size_t)tb * BB + b) * 128 + threadIdx.x] = acc;
}

__global__ void context_combine_kernel(float* __restrict__ ctx) {
    int i = blockIdx.x * blockDim.x + threadIdx.x;   // 0..BB*HH-1
    float s = 0.0f;
#pragma unroll
    for (int cpt = 0; cpt < 16; cpt++)
        s += g_cpart[cpt * BB * HH + i];
    ctx[i] = s;
}

// ---------------- launch ----------------
extern "C" void kernel_launch(void* const* d_in, const int* in_sizes, int n_in,
                              void* d_out, int out_size) {
    const float* X    = (const float*)d_in[0];
    const float* Wa_w = (const float*)d_in[1];
    const float* Wa_b = (const float*)d_in[2];
    const float* Ua_w = (const float*)d_in[3];
    const float* Ua_b = (const float*)d_in[4];
    const float* Va_w = (const float*)d_in[5];
    // d_in[6] (Va_b) unused: softmax is shift-invariant.
    (void)in_sizes; (void)n_in; (void)out_size;

    float* out = (float*)d_out;
    float* ctx = out;                 // [B, H]
    float* aw  = out + BB * HH;       // [B, T]

    cudaFuncSetAttribute(score_kernel, cudaFuncAttributeMaxDynamicSharedMemorySize, SM_DYN);

    prepX_kernel<<<16384, 256>>>(X);
    prep_kernel<<<(HH * HH + 255) / 256, 256>>>(Wa_w, Wa_b, Ua_w, Ua_b, Va_w);
    score_kernel<<<MM / 128, 256, SM_DYN>>>();
    softmax_kernel<<<BB, 256>>>(aw);
    context_part_kernel<<<BB * 16, 128>>>(X, aw);
    context_combine_kernel<<<BB * HH / 256, 256>>>(ctx);
}

// round 16
// speedup vs baseline: 1.3299x; 1.3299x over previous
#include <cuda_runtime.h>
#include <cstdint>

#define BB 128
#define TT 2048
#define HH 512
#define MM (BB*TT)

// ---------------- device scratch (no allocations allowed) ----------------
__device__ __align__(16) float g_Wsum[HH*HH];      // Wa+Ua, pre-rounded to tf32
__device__ __align__(16) float2 g_vb[HH];          // {v[o], bsum[o]*2*log2(e)}
__device__ float g_score[MM];
__device__ __align__(16) float g_cpart[16*BB*HH];

#define SW128(o) ((o) ^ (((o) >> 3) & 0x70))
#define TWO_LOG2E 2.885390081777927f

__device__ __forceinline__ uint32_t smem_u32(const void* p) {
    uint32_t a;
    asm("{ .reg .u64 t; cvta.to.shared.u64 t, %1; cvt.u32.u64 %0, t; }" : "=r"(a) : "l"(p));
    return a;
}
__device__ __forceinline__ uint32_t lds32(uint32_t addr) {
    uint32_t v;
    asm volatile("ld.shared.b32 %0, [%1];" : "=r"(v) : "r"(addr));
    return v;
}
__device__ __forceinline__ uint32_t lds32_tf32(uint32_t addr) {
    uint32_t v = lds32(addr);
    asm("cvt.rna.tf32.f32 %0, %1;" : "=r"(v) : "r"(v));
    return v;
}
__device__ __forceinline__ void mma_tf32(float* c, const uint32_t* a, const uint32_t* b) {
    asm volatile("mma.sync.aligned.m16n8k8.row.col.f32.tf32.tf32.f32 "
                 "{%0,%1,%2,%3}, {%4,%5,%6,%7}, {%8,%9}, {%0,%1,%2,%3};"
                 : "+f"(c[0]), "+f"(c[1]), "+f"(c[2]), "+f"(c[3])
                 : "r"(a[0]), "r"(a[1]), "r"(a[2]), "r"(a[3]), "r"(b[0]), "r"(b[1]));
}
__device__ __forceinline__ void cpasync16(uint32_t saddr, const void* gptr) {
    asm volatile("cp.async.cg.shared.global [%0], [%1], 16;" :: "r"(saddr), "l"(gptr) : "memory");
}

// ---------------- K1: prep — Wsum (tf32-rounded) + vb table ----------------
__global__ void prep_kernel(const float* __restrict__ Wa_w, const float* __restrict__ Wa_b,
                            const float* __restrict__ Ua_w, const float* __restrict__ Ua_b,
                            const float* __restrict__ Va_w) {
    int i = blockIdx.x * blockDim.x + threadIdx.x;
    if (i < HH * HH) {
        float w = Wa_w[i] + Ua_w[i];
        uint32_t t;
        asm("cvt.rna.tf32.f32 %0, %1;" : "=r"(t) : "f"(w));   // pre-round to tf32
        g_Wsum[i] = __uint_as_float(t);
    }
    if (i < HH) {
        float b = Wa_b[i] + Ua_b[i];
        g_vb[i] = make_float2(Va_w[i], b * TWO_LOG2E);
    }
}

// ---------------- K2: fused score GEMM, tf32 single-term, 3-stage cp.async ----------------
// score[m] = sum_o v[o] * tanh(bsum[o] + sum_k X[m,k]*Wsum[o,k])
// CTA: M=128, flat loop over 64 chunks: g = nb*16 + kc (4 N-passes x 16 K-chunks of 32).
// A tile: 128 rows x 32 fp32 = 16KB (128B rows, SW128). B tile same from g_Wsum.
// SMEM: 3 stages x 32KB = 96KB. 2 CTAs/SM (128-reg cap).
// A streams straight from X (no conversion pre-pass); W pre-rounded in prep.

#define SM_DYN (3*32768 + 1024)

__device__ __forceinline__ void cpA(uint32_t stage, const float* __restrict__ X,
                                    size_t m_base, int kc, int tid) {
#pragma unroll
    for (int i = 0; i < 4; i++) {
        int u  = tid + i * 256;          // 0..1023 = m*8 + uu
        int m  = u >> 3;
        int uu = u & 7;
        const float* src = X + (m_base + m) * HH + kc * 32 + uu * 4;
        cpasync16(stage + SW128(m * 128 + uu * 16), src);
    }
}

__device__ __forceinline__ void cpB(uint32_t stage, int nb, int kc, int tid) {
    const uint32_t B = stage + 16384;
#pragma unroll
    for (int i = 0; i < 4; i++) {
        int u  = tid + i * 256;          // 0..1023 = o*8 + uu
        int o  = u >> 3;
        int uu = u & 7;
        const float* src = g_Wsum + (size_t)(nb * 128 + o) * HH + kc * 32 + uu * 4;
        cpasync16(B + SW128(o * 128 + uu * 16), src);
    }
}

__global__ __launch_bounds__(256, 2)
void score_kernel(const float* __restrict__ X) {
    extern __shared__ __align__(1024) char smem[];
    __shared__ float score_sm[128];
    const uint32_t sb = smem_u32(smem);
    const uint32_t abase = (sb + 1023u) & ~1023u;   // 1024-aligned stage base
    const int tid  = threadIdx.x;
    const int lane = tid & 31;
    const int wid  = tid >> 5;
    const int wm   = wid & 3;                        // m-warp 0..3 (32 rows each)
    const int wn   = wid >> 2;                       // n-warp 0..1 (64 cols each)
    const int tg   = lane >> 2;                      // 0..7
    const int tq   = lane & 3;                       // 0..3
    const size_t m_base = (size_t)blockIdx.x * 128;

    if (tid < 128) score_sm[tid] = 0.0f;

    // Fragment addressing (all fragment rows have row&7 == tg -> uniform swizzle XOR)
    const uint32_t rxor = (uint32_t)(tg << 4);               // byte XOR within row
    const uint32_t roA  = (uint32_t)((wm * 32 + tg) * 128);  // mf=0 row base; mf=1 -> +2048
    uint32_t roB[8];
#pragma unroll
    for (int nf = 0; nf < 8; nf++)
        roB[nf] = (uint32_t)((wn * 64 + nf * 8 + tg) * 128);

    float c[2][8][4];

    // prologue: prefetch chunks 0 and 1
    cpA(abase, X, m_base, 0, tid);          cpB(abase, 0, 0, tid);
    asm volatile("cp.async.commit_group;");
    cpA(abase + 32768, X, m_base, 1, tid);  cpB(abase + 32768, 0, 1, tid);
    asm volatile("cp.async.commit_group;");

    for (int g = 0; g < 64; g++) {
        const int kc = g & 15;
        const int nb = g >> 4;
        const uint32_t stage = abase + (uint32_t)(g % 3) * 32768;

        asm volatile("cp.async.wait_group 1;" ::: "memory");
        __syncthreads();   // stage data visible; all warps done with chunk g-1

        if (g + 2 < 64) {
            const int g2 = g + 2;
            const uint32_t st2 = abase + (uint32_t)(g2 % 3) * 32768;
            cpA(st2, X, m_base, g2 & 15, tid);
            cpB(st2, g2 >> 4, g2 & 15, tid);
            asm volatile("cp.async.commit_group;");
        }

        if (kc == 0) {
#pragma unroll
            for (int mf = 0; mf < 2; mf++)
#pragma unroll
                for (int nf = 0; nf < 8; nf++)
#pragma unroll
                    for (int q = 0; q < 4; q++) c[mf][nf][q] = 0.0f;
        }

        const uint32_t A = stage;
        const uint32_t B = stage + 16384;
#pragma unroll
        for (int s = 0; s < 4; s++) {
            const uint32_t k0 = (uint32_t)(s * 32 + tq * 4);        // byte offset of col
            const uint32_t c0 = k0 ^ rxor;                          // swizzled col (a0/a1, b0)
            const uint32_t c1 = (k0 + 16) ^ rxor;                   // col+4 (a2/a3, b1)

            uint32_t a[2][4];
#pragma unroll
            for (int mf = 0; mf < 2; mf++) {
                const uint32_t r = A + roA + (uint32_t)(mf * 2048);
                a[mf][0] = lds32_tf32(r + c0);                      // (row,   col)
                a[mf][1] = lds32_tf32(r + 1024 + c0);               // (row+8, col)
                a[mf][2] = lds32_tf32(r + c1);                      // (row,   col+4)
                a[mf][3] = lds32_tf32(r + 1024 + c1);               // (row+8, col+4)
            }
            uint32_t b[8][2];
#pragma unroll
            for (int nf = 0; nf < 8; nf++) {
                b[nf][0] = lds32(B + roB[nf] + c0);                 // (k,   n)
                b[nf][1] = lds32(B + roB[nf] + c1);                 // (k+4, n)
            }
#pragma unroll
            for (int mf = 0; mf < 2; mf++)
#pragma unroll
                for (int nf = 0; nf < 8; nf++)
                    mma_tf32(c[mf][nf], a[mf], b[nf]);
        }

        if (kc == 15) {
            // fused epilogue for pass nb: score += v[o]*tanh(acc + b[o])
#pragma unroll
            for (int mf = 0; mf < 2; mf++) {
                float s0 = 0.0f, s1 = 0.0f;
#pragma unroll
                for (int nf = 0; nf < 8; nf++) {
#pragma unroll
                    for (int col = 0; col < 2; col++) {
                        int o = nb * 128 + wn * 64 + nf * 8 + tq * 2 + col;
                        float2 vbv = __ldg(&g_vb[o]);
                        float x0 = fmaf(c[mf][nf][col],     TWO_LOG2E, vbv.y);
                        float x1 = fmaf(c[mf][nf][col + 2], TWO_LOG2E, vbv.y);
                        float e0, e1, r0, r1;
                        asm("ex2.approx.f32 %0, %1;" : "=f"(e0) : "f"(x0));
                        asm("ex2.approx.f32 %0, %1;" : "=f"(e1) : "f"(x1));
                        asm("rcp.approx.f32 %0, %1;" : "=f"(r0) : "f"(e0 + 1.0f));
                        asm("rcp.approx.f32 %0, %1;" : "=f"(r1) : "f"(e1 + 1.0f));
                        s0 += vbv.x - 2.0f * vbv.x * r0;   // v*tanh
                        s1 += vbv.x - 2.0f * vbv.x * r1;
                    }
                }
                s0 += __shfl_xor_sync(0xffffffffu, s0, 1);
                s0 += __shfl_xor_sync(0xffffffffu, s0, 2);
                s1 += __shfl_xor_sync(0xffffffffu, s1, 1);
                s1 += __shfl_xor_sync(0xffffffffu, s1, 2);
                if (tq == 0) {
                    int r = wm * 32 + mf * 16 + tg;
                    atomicAdd(&score_sm[r], s0);
                    atomicAdd(&score_sm[r + 8], s1);
                }
            }
        }
    }

    __syncthreads();
    if (tid < 128) g_score[m_base + tid] = score_sm[tid];
}

// ---------------- K3: per-batch softmax over T ----------------
__global__ void softmax_kernel(float* __restrict__ aw_out) {
    __shared__ float sh[TT];
    __shared__ float red[256];
    const int b = blockIdx.x;
    const int tid = threadIdx.x;
    const float* s = g_score + (size_t)b * TT;

    float mx = -1e30f;
    for (int t = tid; t < TT; t += 256) {
        float v = s[t];
        sh[t] = v;
        mx = fmaxf(mx, v);
    }
    red[tid] = mx;
    __syncthreads();
    for (int o = 128; o > 0; o >>= 1) {
        if (tid < o) red[tid] = fmaxf(red[tid], red[tid + o]);
        __syncthreads();
    }
    mx = red[0];
    __syncthreads();

    float sum = 0.0f;
    for (int t = tid; t < TT; t += 256) {
        float e = __expf(sh[t] - mx);
        sh[t] = e;
        sum += e;
    }
    red[tid] = sum;
    __syncthreads();
    for (int o = 128; o > 0; o >>= 1) {
        if (tid < o) red[tid] += red[tid + o];
        __syncthreads();
    }
    float inv = 1.0f / red[0];
    for (int t = tid; t < TT; t += 256)
        aw_out[(size_t)b * TT + t] = sh[t] * inv;
}

// ---------------- K4: context partials (float4/thread), 16 T-chunks ----------------
__global__ void context_part_kernel(const float* __restrict__ X,
                                    const float* __restrict__ aw) {
    const int blk = blockIdx.x;           // b*16 + tb
    const int b  = blk >> 4;
    const int tb = blk & 15;
    const float4* xp = (const float4*)(X + (size_t)b * TT * HH + (size_t)tb * 128 * HH)
                       + threadIdx.x;     // thread covers h = tid*4..tid*4+3
    const float* a = aw + (size_t)b * TT + tb * 128;

    float4 acc = make_float4(0.f, 0.f, 0.f, 0.f);
#pragma unroll 8
    for (int t = 0; t < 128; t++) {
        float av = a[t];
        float4 x = xp[(size_t)t * 128];
        acc.x = fmaf(av, x.x, acc.x);
        acc.y = fmaf(av, x.y, acc.y);
        acc.z = fmaf(av, x.z, acc.z);
        acc.w = fmaf(av, x.w, acc.w);
    }
    ((float4*)g_cpart)[((size_t)tb * BB + b) * 128 + threadIdx.x] = acc;
}

__global__ void context_combine_kernel(float* __restrict__ ctx) {
    int i = blockIdx.x * blockDim.x + threadIdx.x;   // 0..BB*HH-1
    float s = 0.0f;
#pragma unroll
    for (int cpt = 0; cpt < 16; cpt++)
        s += g_cpart[cpt * BB * HH + i];
    ctx[i] = s;
}

// ---------------- launch ----------------
extern "C" void kernel_launch(void* const* d_in, const int* in_sizes, int n_in,
                              void* d_out, int out_size) {
    const float* X    = (const float*)d_in[0];
    const float* Wa_w = (const float*)d_in[1];
    const float* Wa_b = (const float*)d_in[2];
    const float* Ua_w = (const float*)d_in[3];
    const float* Ua_b = (const float*)d_in[4];
    const float* Va_w = (const float*)d_in[5];
    // d_in[6] (Va_b) unused: softmax is shift-invariant.
    (void)in_sizes; (void)n_in; (void)out_size;

    float* out = (float*)d_out;
    float* ctx = out;                 // [B, H]
    float* aw  = out + BB * HH;       // [B, T]

    cudaFuncSetAttribute(score_kernel, cudaFuncAttributeMaxDynamicSharedMemorySize, SM_DYN);

    prep_kernel<<<(HH * HH + 255) / 256, 256>>>(Wa_w, Wa_b, Ua_w, Ua_b, Va_w);
    score_kernel<<<MM / 128, 256, SM_DYN>>>(X);
    softmax_kernel<<<BB, 256>>>(aw);
    context_part_kernel<<<BB * 16, 128>>>(X, aw);
    context_combine_kernel<<<BB * HH / 256, 256>>>(ctx);
}